// round 16
// baseline (speedup 1.0000x reference)
#include <cuda_runtime.h>

// Problem dimensions (fixed by the reference setup)
#define BB 4
#define LL 4096
#define DD 128
#define NN 16
#define TT 16               // chunk length
#define NC (LL / TT)        // 256 chunks per batch
#define DT_OFF 0.1f

typedef unsigned long long u64;

// Scratch (device globals — no allocation allowed)
__device__ __align__(16) float g_coef[BB * LL * 48];        // per-(b,l): e[16],w[16],C[16]
__device__ __align__(16) float g_Et[BB * NN * NC * DD];     // end states, TRANSPOSED [b][n][c][d]
__device__ __align__(16) float g_H0t[BB * NN * NC * DD];    // carry-ins,  TRANSPOSED [b][n][c][d]
__device__ float g_P[BB * NC * NN];                          // chunk decay products [b][c][n]

// ---------------- packed f32x2 helpers ----------------
__device__ __forceinline__ u64 fma2(u64 a, u64 b, u64 c) {
    u64 d; asm("fma.rn.f32x2 %0, %1, %2, %3;" : "=l"(d) : "l"(a), "l"(b), "l"(c));
    return d;
}
__device__ __forceinline__ u64 mul2(u64 a, u64 b) {
    u64 d; asm("mul.rn.f32x2 %0, %1, %2;" : "=l"(d) : "l"(a), "l"(b));
    return d;
}
__device__ __forceinline__ u64 pack2(float lo, float hi) {
    u64 d;
    asm("mov.b64 %0, {%1, %2};" : "=l"(d)
        : "r"(__float_as_uint(lo)), "r"(__float_as_uint(hi)));
    return d;
}
__device__ __forceinline__ float2 unpack2(u64 v) {
    unsigned int lo, hi;
    asm("mov.b64 {%0, %1}, %2;" : "=r"(lo), "=r"(hi) : "l"(v));
    return make_float2(__uint_as_float(lo), __uint_as_float(hi));
}

// ---------------------------------------------------------------------------
// K1 (j-split): 8 threads per position. Thread q owns 4 COMPLETE dot products
// (rows j = 4q..4q+3 of [Wb;Wc]) over all 128 dims — no reduction shfl needed.
// The shared delta-dot (row 32 = Wd) is split 16 dims/thread + 3-level shfl.
// W bank rotation: index (i+q)&31 puts the 8 lanes on 8 distinct float4-banks.
// Epilogue: q<4 produce e/w for n=4q..4q+3; q>=4 produce C for n=4(q-4)..+3.
// ---------------------------------------------------------------------------
__global__ __launch_bounds__(128) void k1_coef(
    const float* __restrict__ x,
    const float* __restrict__ A,
    const float* __restrict__ Wb, const float* __restrict__ bb,
    const float* __restrict__ Wc, const float* __restrict__ bc,
    const float* __restrict__ Wd, const float* __restrict__ bd)
{
    __shared__ __align__(16) float sW[33 * 128];
    __shared__ float sb[33];
    __shared__ float sA[16];

    int tid = threadIdx.x;
    for (int i = tid; i < 2048; i += 128) {
        sW[i]        = Wb[i];
        sW[2048 + i] = Wc[i];
    }
    sW[4096 + tid] = Wd[tid];
    if (tid < 16) { sb[tid] = bb[tid]; sb[16 + tid] = bc[tid]; sA[tid] = A[tid]; }
    if (tid == 0) sb[32] = bd[0];
    __syncthreads();

    int pos = blockIdx.x * 16 + (tid >> 3);   // (b*L + l), 0..16383
    int q   = tid & 7;                         // j-group / lane role

    const float4* xr = (const float4*)(x + (size_t)pos * DD);
    const float4* W4 = (const float4*)sW;

    // ---- delta partial dot: dims 16q..16q+15 ----
    float accd = 0.f;
    {
        const float4* Wd4 = W4 + 1024;        // row 32 (offset 4096 floats)
#pragma unroll
        for (int ii = 0; ii < 4; ii++) {
            int i = 4 * q + ii;
            float4 xv = xr[i];
            float4 wv = Wd4[i];
            accd = fmaf(xv.w, wv.w, fmaf(xv.z, wv.z,
                   fmaf(xv.y, wv.y, fmaf(xv.x, wv.x, accd))));
        }
    }

    // ---- 4 complete dots (rows j0..j0+3) over all 128 dims ----
    int j0 = q * 4;
    float acc[4] = {0.f, 0.f, 0.f, 0.f};
#pragma unroll 4
    for (int i = 0; i < 32; i++) {
        int ir = (i + q) & 31;                // bank rotation: lanes -> 8 banks
        float4 xv = xr[ir];
#pragma unroll
        for (int jj = 0; jj < 4; jj++) {
            float4 wv = W4[(j0 + jj) * 32 + ir];
            acc[jj] = fmaf(xv.w, wv.w, fmaf(xv.z, wv.z,
                      fmaf(xv.y, wv.y, fmaf(xv.x, wv.x, acc[jj]))));
        }
    }

    // ---- delta reduction across the 8 lanes of this position ----
    accd += __shfl_xor_sync(0xffffffffu, accd, 1);
    accd += __shfl_xor_sync(0xffffffffu, accd, 2);
    accd += __shfl_xor_sync(0xffffffffu, accd, 4);

    float z = accd + sb[32];
    float delta = fmaxf(z, 0.f) + __logf(1.0f + __expf(-fabsf(z))) + DT_OFF;

    float* o = g_coef + (size_t)pos * 48;
    if (q < 4) {
        int n0 = j0;                           // n = 4q..4q+3  (Bp rows)
        float4 eo, wo;
#pragma unroll
        for (int k = 0; k < 4; k++) {
            int n = n0 + k;
            float da = delta * sA[n];
            float e  = __expf(da);
            float em = __expf(-da);
            ((float*)&eo)[k] = e;
            ((float*)&wo)[k] = (1.0f - em) * delta * (acc[k] + sb[n]);
        }
        *(float4*)(o + n0)      = eo;
        *(float4*)(o + 16 + n0) = wo;
    } else {
        int n0 = j0 - 16;                      // n = 4(q-4)..+3  (C rows)
        float4 co;
#pragma unroll
        for (int k = 0; k < 4; k++)
            ((float*)&co)[k] = acc[k] + sb[16 + n0 + k];
        *(float4*)(o + 32 + n0) = co;
    }
}

// ---------------------------------------------------------------------------
// K2: chunk-local scan, h=0 init. 256-thread blocks: thread = (d, n-half).
// Pipelined like K3: e/w rows for step t+1 prefetched into registers while
// step t computes (full unroll). Coefficients compacted to 32 floats/step
// (e,w only — C unused here). x staged via coalesced smem.
// End states written TRANSPOSED to g_Et[b][n][c][d].
// ---------------------------------------------------------------------------
__global__ __launch_bounds__(256, 4) void k2_local(const float* __restrict__ x)
{
    __shared__ __align__(16) float sc[TT * 32];    // e[16],w[16] per step
    __shared__ __align__(16) float sx[TT * DD];
    int c = blockIdx.x, b = blockIdx.y;
    int tid = threadIdx.x;
    int d  = tid >> 1;
    int nh = tid & 1;

    // stage x chunk (coalesced float4)
    const float4* xg = (const float4*)(x + (size_t)(b * LL + c * TT) * DD);
    float4* sx4 = (float4*)sx;
    sx4[tid]       = xg[tid];
    sx4[tid + 256] = xg[tid + 256];

    // compacted coef copy: keep only e/w (first 8 float4 of each 12)
    const float4* csrc = (const float4*)(g_coef + (size_t)(b * LL + c * TT) * 48);
    float4* cdst = (float4*)sc;
    if (tid < 128) {
        int pos = tid >> 3, comp = tid & 7;
        cdst[pos * 8 + comp] = csrc[pos * 12 + comp];
    }
    __syncthreads();

    u64 h[4];
#pragma unroll
    for (int i = 0; i < 4; i++) h[i] = 0ull;

    const ulonglong2* rows = (const ulonglong2*)sc;   // 8 ulonglong2 per t
    int ro = nh * 2;

    // prefetch step 0's e/w rows
    ulonglong2 pe_a = rows[ro],     pe_b = rows[ro + 1];
    ulonglong2 pw_a = rows[4 + ro], pw_b = rows[5 + ro];

#pragma unroll
    for (int t = 0; t < TT; t++) {
        ulonglong2 e2a = pe_a, e2b = pe_b, w2a = pw_a, w2b = pw_b;
        if (t + 1 < TT) {                      // prefetch next e/w
            const ulonglong2* nrow = rows + (t + 1) * 8;
            pe_a = nrow[ro];     pe_b = nrow[ro + 1];
            pw_a = nrow[4 + ro]; pw_b = nrow[5 + ro];
        }

        float xt = sx[t * DD + d];
        u64 x2 = pack2(xt, xt);

        h[0] = fma2(e2a.x, h[0], mul2(w2a.x, x2));
        h[1] = fma2(e2a.y, h[1], mul2(w2a.y, x2));
        h[2] = fma2(e2b.x, h[2], mul2(w2b.x, x2));
        h[3] = fma2(e2b.y, h[3], mul2(w2b.y, x2));
    }

    // transposed store: Et[b][n][c][d]
    int n0 = nh * 8;
    size_t base = ((size_t)(b * NN + n0) * NC + c) * DD + d;
#pragma unroll
    for (int i = 0; i < 4; i++) {
        float2 v = unpack2(h[i]);
        g_Et[base + (size_t)(2 * i)     * NC * DD] = v.x;
        g_Et[base + (size_t)(2 * i + 1) * NC * DD] = v.y;
    }

    if (tid < 16) {
        float p = 1.f;
#pragma unroll
        for (int t = 0; t < TT; t++) p *= sc[t * 32 + tid];
        g_P[(b * NC + c) * NN + tid] = p;
    }
}

// ---------------------------------------------------------------------------
// K2.5: inter-chunk combine. One block per (b,n); 128 threads = d.
// Slab Et[b][n][:][:] (128 KB) processed in four 32 KB smem stages
// (independent coalesced loads -> full MLP); 256-step serial scan in
// smem/registers; carry-ins stream out coalesced to H0t[b][n][c][d].
// ---------------------------------------------------------------------------
__global__ __launch_bounds__(128) void k25_merged()
{
    __shared__ __align__(16) float sE[64 * DD];   // 32 KB stage
    __shared__ float sp[NC];

    int n = blockIdx.x, b = blockIdx.y;
    int d = threadIdx.x;

    sp[d]       = g_P[(b * NC + d) * NN + n];
    sp[d + 128] = g_P[(b * NC + d + 128) * NN + n];

    const float* Et  = g_Et  + (size_t)(b * NN + n) * NC * DD;
    float*       H0t = g_H0t + (size_t)(b * NN + n) * NC * DD;

    float h = 0.f;
#pragma unroll
    for (int stage = 0; stage < 4; stage++) {
#pragma unroll
        for (int j = 0; j < 64; j++)
            sE[j * DD + d] = Et[(size_t)(stage * 64 + j) * DD + d];
        __syncthreads();
#pragma unroll
        for (int j = 0; j < 64; j++) {
            int c = stage * 64 + j;
            H0t[(size_t)c * DD + d] = h;          // fire-and-forget
            h = fmaf(sp[c], h, sE[j * DD + d]);
        }
        __syncthreads();
    }
}

// ---------------------------------------------------------------------------
// K3: final scan with carry-in; y[b,l,d] = sum_n C[l,n]*h[n].
// 256-thread blocks, thread = (d, n-half). Software-pipelined: e/w rows for
// step t+1 are prefetched into registers while step t computes (full unroll).
// x staged through smem. __launch_bounds__(256,4) -> 64-reg budget.
// ---------------------------------------------------------------------------
__global__ __launch_bounds__(256, 4) void k3_scan(const float* __restrict__ x,
                                                  float* __restrict__ y)
{
    __shared__ __align__(16) float sc[TT * 48];
    __shared__ __align__(16) float sx[TT * DD];
    int c = blockIdx.x, b = blockIdx.y;
    int tid = threadIdx.x;
    int d  = tid >> 1;
    int nh = tid & 1;

    // stage x chunk (coalesced float4) and coef rows
    const float4* xg = (const float4*)(x + (size_t)(b * LL + c * TT) * DD);
    float4* sx4 = (float4*)sx;
    sx4[tid]       = xg[tid];
    sx4[tid + 256] = xg[tid + 256];

    const float4* csrc = (const float4*)(g_coef + (size_t)(b * LL + c * TT) * 48);
    float4* cdst = (float4*)sc;
    if (tid < 192) cdst[tid] = csrc[tid];

    // carry-in from transposed H0t[b][n][c][d]
    u64 h[4];
    {
        int n0 = nh * 8;
        size_t base = ((size_t)(b * NN + n0) * NC + c) * DD + d;
#pragma unroll
        for (int i = 0; i < 4; i++) {
            float lo = g_H0t[base + (size_t)(2 * i)     * NC * DD];
            float hi = g_H0t[base + (size_t)(2 * i + 1) * NC * DD];
            h[i] = pack2(lo, hi);
        }
    }
    __syncthreads();

    float* yp = y + (size_t)(b * LL + c * TT) * DD + d;

    const ulonglong2* rows = (const ulonglong2*)sc;   // 12 ulonglong2 per t
    int ro = nh * 2;

    // prefetch step 0's e/w rows
    ulonglong2 pe_a = rows[ro],     pe_b = rows[ro + 1];
    ulonglong2 pw_a = rows[4 + ro], pw_b = rows[5 + ro];

#pragma unroll
    for (int t = 0; t < TT; t++) {
        ulonglong2 e2a = pe_a, e2b = pe_b, w2a = pw_a, w2b = pw_b;
        ulonglong2 c2a = rows[t * 12 + 8 + ro];
        ulonglong2 c2b = rows[t * 12 + 9 + ro];
        if (t + 1 < TT) {                      // prefetch next e/w
            const ulonglong2* nrow = rows + (t + 1) * 12;
            pe_a = nrow[ro];     pe_b = nrow[ro + 1];
            pw_a = nrow[4 + ro]; pw_b = nrow[5 + ro];
        }

        float xt = sx[t * DD + d];
        u64 x2 = pack2(xt, xt);

        h[0] = fma2(e2a.x, h[0], mul2(w2a.x, x2));
        h[1] = fma2(e2a.y, h[1], mul2(w2a.y, x2));
        h[2] = fma2(e2b.x, h[2], mul2(w2b.x, x2));
        h[3] = fma2(e2b.y, h[3], mul2(w2b.y, x2));

        u64 a0 = 0ull, a1 = 0ull;
        a0 = fma2(c2a.x, h[0], a0);
        a1 = fma2(c2a.y, h[1], a1);
        a0 = fma2(c2b.x, h[2], a0);
        a1 = fma2(c2b.y, h[3], a1);
        float2 p0 = unpack2(a0), p1 = unpack2(a1);
        float part = (p0.x + p0.y) + (p1.x + p1.y);
        float other = __shfl_xor_sync(0xffffffffu, part, 1);
        if (nh == 0) yp[t * DD] = part + other;
    }
}

// ---------------------------------------------------------------------------
extern "C" void kernel_launch(void* const* d_in, const int* in_sizes, int n_in,
                              void* d_out, int out_size)
{
    const float* x  = (const float*)d_in[0];
    const float* A  = (const float*)d_in[1];
    const float* Wb = (const float*)d_in[2];
    const float* bb = (const float*)d_in[3];
    const float* Wc = (const float*)d_in[4];
    const float* bc = (const float*)d_in[5];
    const float* Wd = (const float*)d_in[6];
    const float* bd = (const float*)d_in[7];
    float* y = (float*)d_out;

    k1_coef<<<1024, 128>>>(x, A, Wb, bb, Wc, bc, Wd, bd);

    dim3 grid(NC, BB);
    k2_local<<<grid, 256>>>(x);

    dim3 cgrid(NN, BB);
    k25_merged<<<cgrid, 128>>>();

    k3_scan<<<grid, 256>>>(x, y);
}

// round 17
// speedup vs baseline: 1.0029x; 1.0029x over previous
#include <cuda_runtime.h>

// Problem dimensions (fixed by the reference setup)
#define BB 4
#define LL 4096
#define DD 128
#define NN 16
#define TT 16               // chunk length
#define NC (LL / TT)        // 256 chunks per batch
#define DT_OFF 0.1f

typedef unsigned long long u64;

// Scratch (device globals — no allocation allowed)
__device__ __align__(16) float g_coef[BB * LL * 48];        // per-(b,l): e[16],w[16],C[16]
__device__ __align__(16) float g_Et[BB * NN * NC * DD];     // end states, TRANSPOSED [b][n][c][d]
__device__ __align__(16) float g_H0t[BB * NN * NC * DD];    // carry-ins,  TRANSPOSED [b][n][c][d]
__device__ float g_P[BB * NC * NN];                          // chunk decay products [b][c][n]

// ---------------- packed f32x2 helpers ----------------
__device__ __forceinline__ u64 fma2(u64 a, u64 b, u64 c) {
    u64 d; asm("fma.rn.f32x2 %0, %1, %2, %3;" : "=l"(d) : "l"(a), "l"(b), "l"(c));
    return d;
}
__device__ __forceinline__ u64 mul2(u64 a, u64 b) {
    u64 d; asm("mul.rn.f32x2 %0, %1, %2;" : "=l"(d) : "l"(a), "l"(b));
    return d;
}
__device__ __forceinline__ u64 pack2(float lo, float hi) {
    u64 d;
    asm("mov.b64 %0, {%1, %2};" : "=l"(d)
        : "r"(__float_as_uint(lo)), "r"(__float_as_uint(hi)));
    return d;
}
__device__ __forceinline__ float2 unpack2(u64 v) {
    unsigned int lo, hi;
    asm("mov.b64 {%0, %1}, %2;" : "=r"(lo), "=r"(hi) : "l"(v));
    return make_float2(__uint_as_float(lo), __uint_as_float(hi));
}

// ---------------------------------------------------------------------------
// K1 (j-split, smem-staged x): 256 threads, 32 positions/block, 8 threads per
// position. x is loaded ONCE coalesced into padded smem (132-float rows): the
// (i+q)&31 rotation then gives each 8-lane LDS.128 phase 8 distinct banks.
// Thread q owns 4 complete rows of [Wb;Wc]; delta dot split 16 dims + 3 shfls.
// ---------------------------------------------------------------------------
__global__ __launch_bounds__(256, 3) void k1_coef(
    const float* __restrict__ x,
    const float* __restrict__ A,
    const float* __restrict__ Wb, const float* __restrict__ bb,
    const float* __restrict__ Wc, const float* __restrict__ bc,
    const float* __restrict__ Wd, const float* __restrict__ bd)
{
    __shared__ __align__(16) float sW[33 * 128];   // 16896 B
    __shared__ __align__(16) float sx[32 * 132];   // 16896 B (padded rows)
    __shared__ float sb[33];
    __shared__ float sA[16];

    int tid = threadIdx.x;
    for (int i = tid; i < 2048; i += 256) {
        sW[i]        = Wb[i];
        sW[2048 + i] = Wc[i];
    }
    if (tid < 128) sW[4096 + tid] = Wd[tid];
    if (tid < 16) { sb[tid] = bb[tid]; sb[16 + tid] = bc[tid]; sA[tid] = A[tid]; }
    if (tid == 0) sb[32] = bd[0];

    // stage 32 x rows coalesced into padded smem (33 float4 per row)
    const float4* xg = (const float4*)(x + (size_t)blockIdx.x * 32 * DD);
    float4* sx4 = (float4*)sx;
#pragma unroll
    for (int i = 0; i < 4; i++) {
        int idx = i * 256 + tid;          // 0..1023 float4
        int row = idx >> 5, col = idx & 31;
        sx4[row * 33 + col] = xg[idx];
    }
    __syncthreads();

    int pl  = tid >> 3;                    // position in block, 0..31
    int q   = tid & 7;                     // j-group / lane role
    int pos = blockIdx.x * 32 + pl;        // (b*L + l)

    const float4* xr = (const float4*)sx + pl * 33;
    const float4* W4 = (const float4*)sW;

    // ---- delta partial dot: dims 16q..16q+15 ----
    float accd = 0.f;
    {
        const float4* Wd4 = W4 + 1024;     // row 32
#pragma unroll
        for (int ii = 0; ii < 4; ii++) {
            int i = 4 * q + ii;
            float4 xv = xr[i];
            float4 wv = Wd4[i];
            accd = fmaf(xv.w, wv.w, fmaf(xv.z, wv.z,
                   fmaf(xv.y, wv.y, fmaf(xv.x, wv.x, accd))));
        }
    }

    // ---- 4 complete dots (rows j0..j0+3) over all 128 dims ----
    int j0 = q * 4;
    float acc[4] = {0.f, 0.f, 0.f, 0.f};
#pragma unroll 8
    for (int i = 0; i < 32; i++) {
        int ir = (i + q) & 31;             // bank rotation within padded row
        float4 xv = xr[ir];
#pragma unroll
        for (int jj = 0; jj < 4; jj++) {
            float4 wv = W4[(j0 + jj) * 32 + ir];
            acc[jj] = fmaf(xv.w, wv.w, fmaf(xv.z, wv.z,
                      fmaf(xv.y, wv.y, fmaf(xv.x, wv.x, acc[jj]))));
        }
    }

    // ---- delta reduction across the 8 lanes of this position ----
    accd += __shfl_xor_sync(0xffffffffu, accd, 1);
    accd += __shfl_xor_sync(0xffffffffu, accd, 2);
    accd += __shfl_xor_sync(0xffffffffu, accd, 4);

    float z = accd + sb[32];
    float delta = fmaxf(z, 0.f) + __logf(1.0f + __expf(-fabsf(z))) + DT_OFF;

    float* o = g_coef + (size_t)pos * 48;
    if (q < 4) {
        int n0 = j0;                       // n = 4q..4q+3  (Bp rows)
        float4 eo, wo;
#pragma unroll
        for (int k = 0; k < 4; k++) {
            int n = n0 + k;
            float da = delta * sA[n];
            float e  = __expf(da);
            float em = __expf(-da);
            ((float*)&eo)[k] = e;
            ((float*)&wo)[k] = (1.0f - em) * delta * (acc[k] + sb[n]);
        }
        *(float4*)(o + n0)      = eo;
        *(float4*)(o + 16 + n0) = wo;
    } else {
        int n0 = j0 - 16;                  // n = 4(q-4)..+3  (C rows)
        float4 co;
#pragma unroll
        for (int k = 0; k < 4; k++)
            ((float*)&co)[k] = acc[k] + sb[16 + n0 + k];
        *(float4*)(o + 32 + n0) = co;
    }
}

// ---------------------------------------------------------------------------
// K2: chunk-local scan, h=0 init. 256-thread blocks: thread = (d, n-half).
// Pipelined: e/w rows for step t+1 prefetched into registers while step t
// computes (full unroll). Coefficients compacted to 32 floats/step (e,w only).
// End states written TRANSPOSED to g_Et[b][n][c][d].
// ---------------------------------------------------------------------------
__global__ __launch_bounds__(256, 4) void k2_local(const float* __restrict__ x)
{
    __shared__ __align__(16) float sc[TT * 32];    // e[16],w[16] per step
    __shared__ __align__(16) float sx[TT * DD];
    int c = blockIdx.x, b = blockIdx.y;
    int tid = threadIdx.x;
    int d  = tid >> 1;
    int nh = tid & 1;

    // stage x chunk (coalesced float4)
    const float4* xg = (const float4*)(x + (size_t)(b * LL + c * TT) * DD);
    float4* sx4 = (float4*)sx;
    sx4[tid]       = xg[tid];
    sx4[tid + 256] = xg[tid + 256];

    // compacted coef copy: keep only e/w (first 8 float4 of each 12)
    const float4* csrc = (const float4*)(g_coef + (size_t)(b * LL + c * TT) * 48);
    float4* cdst = (float4*)sc;
    if (tid < 128) {
        int pos = tid >> 3, comp = tid & 7;
        cdst[pos * 8 + comp] = csrc[pos * 12 + comp];
    }
    __syncthreads();

    u64 h[4];
#pragma unroll
    for (int i = 0; i < 4; i++) h[i] = 0ull;

    const ulonglong2* rows = (const ulonglong2*)sc;   // 8 ulonglong2 per t
    int ro = nh * 2;

    // prefetch step 0's e/w rows
    ulonglong2 pe_a = rows[ro],     pe_b = rows[ro + 1];
    ulonglong2 pw_a = rows[4 + ro], pw_b = rows[5 + ro];

#pragma unroll
    for (int t = 0; t < TT; t++) {
        ulonglong2 e2a = pe_a, e2b = pe_b, w2a = pw_a, w2b = pw_b;
        if (t + 1 < TT) {                      // prefetch next e/w
            const ulonglong2* nrow = rows + (t + 1) * 8;
            pe_a = nrow[ro];     pe_b = nrow[ro + 1];
            pw_a = nrow[4 + ro]; pw_b = nrow[5 + ro];
        }

        float xt = sx[t * DD + d];
        u64 x2 = pack2(xt, xt);

        h[0] = fma2(e2a.x, h[0], mul2(w2a.x, x2));
        h[1] = fma2(e2a.y, h[1], mul2(w2a.y, x2));
        h[2] = fma2(e2b.x, h[2], mul2(w2b.x, x2));
        h[3] = fma2(e2b.y, h[3], mul2(w2b.y, x2));
    }

    // transposed store: Et[b][n][c][d]
    int n0 = nh * 8;
    size_t base = ((size_t)(b * NN + n0) * NC + c) * DD + d;
#pragma unroll
    for (int i = 0; i < 4; i++) {
        float2 v = unpack2(h[i]);
        g_Et[base + (size_t)(2 * i)     * NC * DD] = v.x;
        g_Et[base + (size_t)(2 * i + 1) * NC * DD] = v.y;
    }

    if (tid < 16) {
        float p = 1.f;
#pragma unroll
        for (int t = 0; t < TT; t++) p *= sc[t * 32 + tid];
        g_P[(b * NC + c) * NN + tid] = p;
    }
}

// ---------------------------------------------------------------------------
// K2.5: inter-chunk combine. One block per (b,n); 128 threads = d.
// Slab Et[b][n][:][:] (128 KB) processed in four 32 KB smem stages
// (independent coalesced loads -> full MLP); 256-step serial scan in
// smem/registers; carry-ins stream out coalesced to H0t[b][n][c][d].
// ---------------------------------------------------------------------------
__global__ __launch_bounds__(128) void k25_merged()
{
    __shared__ __align__(16) float sE[64 * DD];   // 32 KB stage
    __shared__ float sp[NC];

    int n = blockIdx.x, b = blockIdx.y;
    int d = threadIdx.x;

    sp[d]       = g_P[(b * NC + d) * NN + n];
    sp[d + 128] = g_P[(b * NC + d + 128) * NN + n];

    const float* Et  = g_Et  + (size_t)(b * NN + n) * NC * DD;
    float*       H0t = g_H0t + (size_t)(b * NN + n) * NC * DD;

    float h = 0.f;
#pragma unroll
    for (int stage = 0; stage < 4; stage++) {
#pragma unroll
        for (int j = 0; j < 64; j++)
            sE[j * DD + d] = Et[(size_t)(stage * 64 + j) * DD + d];
        __syncthreads();
#pragma unroll
        for (int j = 0; j < 64; j++) {
            int c = stage * 64 + j;
            H0t[(size_t)c * DD + d] = h;          // fire-and-forget
            h = fmaf(sp[c], h, sE[j * DD + d]);
        }
        __syncthreads();
    }
}

// ---------------------------------------------------------------------------
// K3: final scan with carry-in; y[b,l,d] = sum_n C[l,n]*h[n].
// 256-thread blocks, thread = (d, n-half). Software-pipelined: e/w AND C rows
// for step t+1 are prefetched into registers while step t computes (full
// unroll) — C was previously loaded in-step with ~20-instr distance (< LDS
// latency); now it gets a full iteration. x staged through smem.
// ---------------------------------------------------------------------------
__global__ __launch_bounds__(256, 4) void k3_scan(const float* __restrict__ x,
                                                  float* __restrict__ y)
{
    __shared__ __align__(16) float sc[TT * 48];
    __shared__ __align__(16) float sx[TT * DD];
    int c = blockIdx.x, b = blockIdx.y;
    int tid = threadIdx.x;
    int d  = tid >> 1;
    int nh = tid & 1;

    // stage x chunk (coalesced float4) and coef rows
    const float4* xg = (const float4*)(x + (size_t)(b * LL + c * TT) * DD);
    float4* sx4 = (float4*)sx;
    sx4[tid]       = xg[tid];
    sx4[tid + 256] = xg[tid + 256];

    const float4* csrc = (const float4*)(g_coef + (size_t)(b * LL + c * TT) * 48);
    float4* cdst = (float4*)sc;
    if (tid < 192) cdst[tid] = csrc[tid];

    // carry-in from transposed H0t[b][n][c][d]
    u64 h[4];
    {
        int n0 = nh * 8;
        size_t base = ((size_t)(b * NN + n0) * NC + c) * DD + d;
#pragma unroll
        for (int i = 0; i < 4; i++) {
            float lo = g_H0t[base + (size_t)(2 * i)     * NC * DD];
            float hi = g_H0t[base + (size_t)(2 * i + 1) * NC * DD];
            h[i] = pack2(lo, hi);
        }
    }
    __syncthreads();

    float* yp = y + (size_t)(b * LL + c * TT) * DD + d;

    const ulonglong2* rows = (const ulonglong2*)sc;   // 12 ulonglong2 per t
    int ro = nh * 2;

    // prefetch step 0's e/w/C rows
    ulonglong2 pe_a = rows[ro],     pe_b = rows[ro + 1];
    ulonglong2 pw_a = rows[4 + ro], pw_b = rows[5 + ro];
    ulonglong2 pc_a = rows[8 + ro], pc_b = rows[9 + ro];

#pragma unroll
    for (int t = 0; t < TT; t++) {
        ulonglong2 e2a = pe_a, e2b = pe_b;
        ulonglong2 w2a = pw_a, w2b = pw_b;
        ulonglong2 c2a = pc_a, c2b = pc_b;
        if (t + 1 < TT) {                      // prefetch next e/w/C
            const ulonglong2* nrow = rows + (t + 1) * 12;
            pe_a = nrow[ro];     pe_b = nrow[ro + 1];
            pw_a = nrow[4 + ro]; pw_b = nrow[5 + ro];
            pc_a = nrow[8 + ro]; pc_b = nrow[9 + ro];
        }

        float xt = sx[t * DD + d];
        u64 x2 = pack2(xt, xt);

        h[0] = fma2(e2a.x, h[0], mul2(w2a.x, x2));
        h[1] = fma2(e2a.y, h[1], mul2(w2a.y, x2));
        h[2] = fma2(e2b.x, h[2], mul2(w2b.x, x2));
        h[3] = fma2(e2b.y, h[3], mul2(w2b.y, x2));

        u64 a0 = 0ull, a1 = 0ull;
        a0 = fma2(c2a.x, h[0], a0);
        a1 = fma2(c2a.y, h[1], a1);
        a0 = fma2(c2b.x, h[2], a0);
        a1 = fma2(c2b.y, h[3], a1);
        float2 p0 = unpack2(a0), p1 = unpack2(a1);
        float part = (p0.x + p0.y) + (p1.x + p1.y);
        float other = __shfl_xor_sync(0xffffffffu, part, 1);
        if (nh == 0) yp[t * DD] = part + other;
    }
}

// ---------------------------------------------------------------------------
extern "C" void kernel_launch(void* const* d_in, const int* in_sizes, int n_in,
                              void* d_out, int out_size)
{
    const float* x  = (const float*)d_in[0];
    const float* A  = (const float*)d_in[1];
    const float* Wb = (const float*)d_in[2];
    const float* bb = (const float*)d_in[3];
    const float* Wc = (const float*)d_in[4];
    const float* bc = (const float*)d_in[5];
    const float* Wd = (const float*)d_in[6];
    const float* bd = (const float*)d_in[7];
    float* y = (float*)d_out;

    k1_coef<<<512, 256>>>(x, A, Wb, bb, Wc, bc, Wd, bd);

    dim3 grid(NC, BB);
    k2_local<<<grid, 256>>>(x);

    dim3 cgrid(NN, BB);
    k25_merged<<<cgrid, 128>>>();

    k3_scan<<<grid, 256>>>(x, y);
}